// round 15
// baseline (speedup 1.0000x reference)
#include <cuda_runtime.h>
#include <cuda_bf16.h>
#include <cstdint>

// ---------------- problem constants ----------------
#define B_SZ   16384
#define NFEAT  32
#define DDIM   64
#define KIN    2048     // NFEAT*DDIM
#define H1     1024
#define H2N    512
#define HOFD   64
#define NPAIRS 496
#define BN_EPS 1e-5f
#define INV_B  (1.0f / 16384.0f)

// ---------------- scratch (device globals; no runtime alloc) ----------------
__device__ __nv_bfloat16 g_xh[(size_t)B_SZ * KIN];
__device__ __nv_bfloat16 g_w1h[(size_t)H1 * KIN];   // [N=H1][K=KIN] transposed
__device__ __nv_bfloat16 g_a1h[(size_t)B_SZ * H1];  // relu(x@W1+b1) bf16, pre-BN
__device__ __nv_bfloat16 g_w2h[(size_t)H2N * H1];   // [N=H2N][K=H1], scale1 folded
__device__ __nv_bfloat16 g_h2[(size_t)B_SZ * H2N];  // relu bf16, pre-BN2
__device__ float g_pd[B_SZ];
__device__ float g_wsym[NFEAT * NFEAT];
__device__ float g_sum1[H1], g_sq1[H1];
__device__ float g_sum2[H2N], g_sq2[H2N];
__device__ float g_b2eff[H2N];
__device__ float g_w3c[H2N + 1];

// ================= PTX helpers (baseline ISA only) ========
__device__ __forceinline__ uint32_t smem_u32(const void* p) {
    uint32_t a;
    asm("{ .reg .u64 t; cvta.to.shared.u64 t, %1; cvt.u32.u64 %0, t; }"
        : "=r"(a) : "l"(p));
    return a;
}
__device__ __forceinline__ void cpa16(uint32_t s, const void* g) {
    asm volatile("cp.async.cg.shared.global [%0], [%1], 16;" :: "r"(s), "l"(g));
}
#define CP_COMMIT() asm volatile("cp.async.commit_group;" ::: "memory")
#define CP_WAIT1()  asm volatile("cp.async.wait_group 1;" ::: "memory")
#define SWZ(o)      ((o) ^ (((o) >> 3) & 0x70))

__device__ __forceinline__ void ldsm4(uint32_t& r0, uint32_t& r1,
                                      uint32_t& r2, uint32_t& r3, uint32_t a) {
    asm volatile("ldmatrix.sync.aligned.m8n8.x4.shared.b16 {%0,%1,%2,%3}, [%4];"
                 : "=r"(r0), "=r"(r1), "=r"(r2), "=r"(r3) : "r"(a));
}
__device__ __forceinline__ void mma16816(float* c,
                                         uint32_t a0, uint32_t a1, uint32_t a2, uint32_t a3,
                                         uint32_t b0, uint32_t b1) {
    asm volatile("mma.sync.aligned.m16n8k16.row.col.f32.bf16.bf16.f32 "
                 "{%0,%1,%2,%3}, {%4,%5,%6,%7}, {%8,%9}, {%0,%1,%2,%3};"
                 : "+f"(c[0]), "+f"(c[1]), "+f"(c[2]), "+f"(c[3])
                 : "r"(a0), "r"(a1), "r"(a2), "r"(a3), "r"(b0), "r"(b1));
}

// ================= bf16 HMMA GEMM + fused BN stats (+ pairdot tail) ========
// 128x128 tile, 8 warps, 3-stage cp.async, 2 CTAs/SM, 1D grid (N-tile fastest).
// If PAIR: blocks >= #tiles run the pair-term quadratic form, tail-filling
// gemm1's last wave (they use the idle fma pipe while tensor drains).
template<int KDIM, int NTOT, bool PAIR>
__global__ __launch_bounds__(256, 2) void gemm_mma(
    const __nv_bfloat16* __restrict__ A,
    const __nv_bfloat16* __restrict__ Bw,
    const float* __restrict__ bias,
    __nv_bfloat16* __restrict__ outH,
    float* __restrict__ sumP, float* __restrict__ sqP,
    const float* __restrict__ x, float* __restrict__ pd)
{
    constexpr int S = 3, BK = 64, BN = 128, BM = 128;
    constexpr int T = KDIM / BK;
    constexpr int NT = NTOT / BN;
    constexpr int GB = NT * (B_SZ / BM);
    constexpr int STAGE_BYTES = (BM + BN) * 128;  // 32KB

    extern __shared__ char smraw[];
    const int tid = threadIdx.x;
    const int wid = tid >> 5, lane = tid & 31;

    if (PAIR && blockIdx.x >= GB) {
        // ---------------- pairdot tail blocks ----------------
        float* Ws = (float*)smraw;
        for (int i = tid; i < NFEAT * NFEAT; i += 256) Ws[i] = g_wsym[i];
        __syncthreads();
        const int b = (blockIdx.x - GB) * 8 + wid;
        const float2* xp = (const float2*)(x + (size_t)b * KIN) + lane;
        float xa[NFEAT], xb[NFEAT];
        #pragma unroll
        for (int n = 0; n < NFEAT; n++) {
            float2 v = xp[n * 32];
            xa[n] = v.x; xb[n] = v.y;
        }
        float acc = 0.f;
        #pragma unroll
        for (int n = 0; n < NFEAT; n++) {
            float ta = 0.f, tb = 0.f;
            const float4* wrow = (const float4*)&Ws[n * NFEAT];
            #pragma unroll
            for (int m4 = 0; m4 < NFEAT / 4; m4++) {
                float4 w = wrow[m4];
                const int m = m4 * 4;
                ta = fmaf(w.x, xa[m + 0], ta); tb = fmaf(w.x, xb[m + 0], tb);
                ta = fmaf(w.y, xa[m + 1], ta); tb = fmaf(w.y, xb[m + 1], tb);
                ta = fmaf(w.z, xa[m + 2], ta); tb = fmaf(w.z, xb[m + 2], tb);
                ta = fmaf(w.w, xa[m + 3], ta); tb = fmaf(w.w, xb[m + 3], tb);
            }
            acc = fmaf(xa[n], ta, acc);
            acc = fmaf(xb[n], tb, acc);
        }
        #pragma unroll
        for (int o = 16; o > 0; o >>= 1)
            acc += __shfl_down_sync(0xffffffffu, acc, o);
        if (lane == 0) pd[b] = acc;
        return;
    }

    // ---------------- gemm path ----------------
    const uint32_t sb = (smem_u32(smraw) + 1023) & ~1023u;
    const int wm0 = (wid >> 2) * 64;
    const int wn0 = (wid & 3) * 32;
    const int n0 = (blockIdx.x % NT) * BN;
    const int m0 = (blockIdx.x / NT) * BM;

    auto load_stage = [&](int gs) {
        const uint32_t sA = sb + (gs % S) * STAGE_BYTES;
        const uint32_t sB = sA + BM * 128;
        const int kk = gs * BK;
        const __nv_bfloat16* Ab = A + (size_t)m0 * KDIM + kk;
        const __nv_bfloat16* Bb = Bw + (size_t)n0 * KDIM + kk;
        #pragma unroll
        for (int t = 0; t < BM * 8 / 256; t++) {
            int c = tid + t * 256;
            int r = c >> 3, ch = c & 7;
            cpa16(sA + SWZ(r * 128 + ch * 16), Ab + (size_t)r * KDIM + ch * 8);
        }
        #pragma unroll
        for (int t = 0; t < BN * 8 / 256; t++) {
            int c = tid + t * 256;
            int r = c >> 3, ch = c & 7;
            cpa16(sB + SWZ(r * 128 + ch * 16), Bb + (size_t)r * KDIM + ch * 8);
        }
    };

    load_stage(0); CP_COMMIT();
    load_stage(1); CP_COMMIT();

    float acc[4][4][4];
    #pragma unroll
    for (int i = 0; i < 4; i++)
        #pragma unroll
        for (int j = 0; j < 4; j++)
            #pragma unroll
            for (int r = 0; r < 4; r++) acc[i][j][r] = 0.f;

    const int aRowOff = (wm0 + (lane & 15)) * 128 + (lane >> 4) * 16;
    const int bRowBase = (wn0 + (lane & 7) + ((lane >> 4) << 3)) * 128 +
                         (((lane >> 3) & 1) << 4);

    for (int i = 0; i < T; ++i) {
        CP_WAIT1();
        __syncthreads();
        const uint32_t sA = sb + (i % S) * STAGE_BYTES;
        const uint32_t sB = sA + BM * 128;
        #pragma unroll
        for (int ks = 0; ks < 4; ks++) {
            const int kb = ks * 32;
            uint32_t a[4][4];
            #pragma unroll
            for (int mi = 0; mi < 4; mi++)
                ldsm4(a[mi][0], a[mi][1], a[mi][2], a[mi][3],
                      sA + SWZ(aRowOff + mi * 16 * 128 + kb));
            uint32_t bf[2][4];
            #pragma unroll
            for (int gg = 0; gg < 2; gg++)
                ldsm4(bf[gg][0], bf[gg][1], bf[gg][2], bf[gg][3],
                      sB + SWZ(bRowBase + gg * 16 * 128 + kb));
            #pragma unroll
            for (int mi = 0; mi < 4; mi++)
                #pragma unroll
                for (int j = 0; j < 4; j++)
                    mma16816(acc[mi][j], a[mi][0], a[mi][1], a[mi][2], a[mi][3],
                             bf[j >> 1][(j & 1) * 2], bf[j >> 1][(j & 1) * 2 + 1]);
        }
        const int ns = i + 2;
        if (ns < T) load_stage(ns);
        CP_COMMIT();
    }

    // epilogue: relu+bias, bf16 store, fused column stats
    float csum[4][2], csq[4][2];
    #pragma unroll
    for (int j = 0; j < 4; j++) { csum[j][0] = csum[j][1] = csq[j][0] = csq[j][1] = 0.f; }

    #pragma unroll
    for (int j = 0; j < 4; j++) {
        const int col = n0 + wn0 + j * 8 + (lane & 3) * 2;
        const float bi0 = bias[col], bi1 = bias[col + 1];
        #pragma unroll
        for (int mi = 0; mi < 4; mi++) {
            const int row = m0 + wm0 + mi * 16 + (lane >> 2);
            #pragma unroll
            for (int h = 0; h < 2; h++) {
                const int rr = row + h * 8;
                const float v0 = fmaxf(acc[mi][j][2 * h + 0] + bi0, 0.f);
                const float v1 = fmaxf(acc[mi][j][2 * h + 1] + bi1, 0.f);
                __nv_bfloat162 ph;
                ph.x = __float2bfloat16(v0);
                ph.y = __float2bfloat16(v1);
                *(__nv_bfloat162*)(outH + (size_t)rr * NTOT + col) = ph;
                csum[j][0] += v0; csq[j][0] = fmaf(v0, v0, csq[j][0]);
                csum[j][1] += v1; csq[j][1] = fmaf(v1, v1, csq[j][1]);
            }
        }
    }
    #pragma unroll
    for (int j = 0; j < 4; j++)
        #pragma unroll
        for (int c = 0; c < 2; c++) {
            #pragma unroll
            for (int o = 16; o >= 4; o >>= 1) {
                csum[j][c] += __shfl_down_sync(0xffffffffu, csum[j][c], o);
                csq[j][c]  += __shfl_down_sync(0xffffffffu, csq[j][c],  o);
            }
        }
    if (lane < 4) {
        #pragma unroll
        for (int j = 0; j < 4; j++)
            #pragma unroll
            for (int c = 0; c < 2; c++) {
                const int col = n0 + wn0 + j * 8 + lane * 2 + c;
                atomicAdd(&sumP[col], csum[j][c]);
                atomicAdd(&sqP[col],  csq[j][c]);
            }
    }
}

// ================= mega prep kernel ========================================
// blocks 0-7: stat zero + b2eff init + wsym + w3c
// blocks 8-2055: W1 transpose->bf16
// blocks 2056+: x -> bf16 (wide copy-convert)
__global__ __launch_bounds__(256) void mega_prep(
    const float* __restrict__ x, const float* __restrict__ W1,
    const float* __restrict__ b2, const float* __restrict__ Wc,
    const float* __restrict__ W3, const float* __restrict__ b3,
    const float* __restrict__ bc,
    __nv_bfloat16* __restrict__ xh, __nv_bfloat16* __restrict__ w1h)
{
    __shared__ float tt[32][33];
    const int t = threadIdx.x;
    const int blk = blockIdx.x;
    if (blk < 8) {
        if (blk < 4) {
            const int i = blk * 256 + t;
            if (i < H1)  { g_sum1[i] = 0.f; g_sq1[i] = 0.f; }
            if (i < H2N) { g_sum2[i] = 0.f; g_sq2[i] = 0.f; g_b2eff[i] = b2[i]; }
        } else if (blk < 6) {
            const int p = (blk - 4) * 256 + t;
            const int d1 = p, d2 = p + 512;
            if ((d1 >> 5) == (d1 & 31)) g_wsym[d1] = 0.f;
            if ((d2 >> 5) == (d2 & 31)) g_wsym[d2] = 0.f;
            if (p < NPAIRS) {
                int i = 0, rem = p;
                while (rem >= NFEAT - 1 - i) { rem -= NFEAT - 1 - i; i++; }
                const int j = i + 1 + rem;
                const float hw = 0.5f * Wc[HOFD + p];
                g_wsym[i * NFEAT + j] = hw;
                g_wsym[j * NFEAT + i] = hw;
            }
        } else {
            const int k = (blk - 6) * 256 + t;
            if (k < H2N) {
                float s = 0.f;
                #pragma unroll
                for (int j = 0; j < HOFD; j++) s += W3[k * HOFD + j] * Wc[j];
                g_w3c[k] = s;
            }
            if (blk == 6 && t == 0) {
                float s = 0.f;
                #pragma unroll
                for (int j = 0; j < HOFD; j++) s += b3[j] * Wc[j];
                g_w3c[H2N] = s + bc[0];
            }
        }
    } else if (blk < 2056) {
        // W1 [KIN][H1] -> w1h [H1][KIN]
        const int id = blk - 8;
        const int lx = t & 31, ly = t >> 5;
        const int n0 = (id & 31) * 32;          // H1/32 = 32 tiles
        const int k0 = (id >> 5) * 32;          // KIN/32 = 64 tiles
        #pragma unroll
        for (int r = 0; r < 4; r++)
            tt[ly + r * 8][lx] = W1[(size_t)(k0 + ly + r * 8) * H1 + n0 + lx];
        __syncthreads();
        #pragma unroll
        for (int r = 0; r < 4; r++) {
            int n = n0 + ly + r * 8;
            w1h[(size_t)n * KIN + k0 + lx] = __float2bfloat16(tt[lx][ly + r * 8]);
        }
    } else {
        // x -> bf16, 8 floats per thread
        const size_t b4 = ((size_t)(blk - 2056) * 256 + t) * 2;  // float4 units
        const float4* xp = (const float4*)x + b4;
        float4 v0 = xp[0], v1 = xp[1];
        __nv_bfloat162 o[4];
        o[0].x = __float2bfloat16(v0.x); o[0].y = __float2bfloat16(v0.y);
        o[1].x = __float2bfloat16(v0.z); o[1].y = __float2bfloat16(v0.w);
        o[2].x = __float2bfloat16(v1.x); o[2].y = __float2bfloat16(v1.y);
        o[3].x = __float2bfloat16(v1.z); o[3].y = __float2bfloat16(v1.w);
        *(uint4*)(xh + b4 * 4) = *(uint4*)o;
    }
}

// ================= fold kernel: BN1 -> W2 / b2eff (stats inline) ===========
// blocks 0-511: W2 transpose with scale1 fold; blocks 512-575: b2eff rank-1
__global__ __launch_bounds__(256) void mega_fold(
    const float* __restrict__ W2, const float* __restrict__ g1,
    const float* __restrict__ beta1, __nv_bfloat16* __restrict__ w2h)
{
    __shared__ float tt[32][33];
    __shared__ float sv[32];
    const int t = threadIdx.x;
    const int lx = t & 31, ly = t >> 5;
    if (blockIdx.x < 512) {
        const int id = blockIdx.x;
        const int n0 = (id & 15) * 32;          // H2N/32 = 16 tiles
        const int k0 = (id >> 4) * 32;          // H1/32 = 32 tiles
        if (t < 32) {
            const int k = k0 + t;
            float m = g_sum1[k] * INV_B;
            float var = g_sq1[k] * INV_B - m * m;
            sv[t] = g1[k] * rsqrtf(var + BN_EPS);
        }
        __syncthreads();
        #pragma unroll
        for (int r = 0; r < 4; r++) {
            const int kk = ly + r * 8;
            tt[kk][lx] = W2[(size_t)(k0 + kk) * H2N + n0 + lx] * sv[kk];
        }
        __syncthreads();
        #pragma unroll
        for (int r = 0; r < 4; r++) {
            int n = n0 + ly + r * 8;
            w2h[(size_t)n * H1 + k0 + lx] = __float2bfloat16(tt[lx][ly + r * 8]);
        }
    } else {
        const int k0 = (blockIdx.x - 512) * 16;
        if (t < 16) {
            const int k = k0 + t;
            float m = g_sum1[k] * INV_B;
            float var = g_sq1[k] * INV_B - m * m;
            float s = g1[k] * rsqrtf(var + BN_EPS);
            sv[t] = beta1[k] - m * s;       // bias1v
        }
        __syncthreads();
        #pragma unroll
        for (int half = 0; half < 2; half++) {
            const int n = t + half * 256;
            float a = 0.f;
            #pragma unroll
            for (int r = 0; r < 16; r++)
                a += sv[r] * W2[(size_t)(k0 + r) * H2N + n];
            atomicAdd(&g_b2eff[n], a);
        }
    }
}

// ================= final: BN2 stats inline + dot + pair term ===============
__global__ __launch_bounds__(256) void final_kernel(
    const __nv_bfloat16* __restrict__ h2, const float* __restrict__ g2,
    const float* __restrict__ beta2, float* __restrict__ out)
{
    __shared__ float sc2[H2N], bv2[H2N];
    const int t = threadIdx.x;
    for (int j = t; j < H2N; j += 256) {
        float m = g_sum2[j] * INV_B;
        float var = g_sq2[j] * INV_B - m * m;
        float s = g2[j] * rsqrtf(var + BN_EPS);
        float w = g_w3c[j];
        sc2[j] = s * w;
        bv2[j] = (beta2[j] - m * s) * w;
    }
    __syncthreads();
    const int wid = t >> 5, lane = t & 31;
    const int gw = blockIdx.x * 8 + wid;
    const __nv_bfloat162* h = (const __nv_bfloat162*)(h2 + (size_t)gw * H2N) + lane;
    float acc = 0.f;
    #pragma unroll
    for (int it = 0; it < H2N / 64; it++) {
        const int k = it * 64 + lane * 2;
        __nv_bfloat162 hv = h[it * 32];
        acc += fmaf(__bfloat162float(hv.x), sc2[k],     bv2[k]);
        acc += fmaf(__bfloat162float(hv.y), sc2[k + 1], bv2[k + 1]);
    }
    #pragma unroll
    for (int o = 16; o > 0; o >>= 1)
        acc += __shfl_down_sync(0xffffffffu, acc, o);
    if (lane == 0) out[gw] = acc + g_w3c[H2N] + g_pd[gw];
}

// ================= launch =================
extern "C" void kernel_launch(void* const* d_in, const int* in_sizes, int n_in,
                              void* d_out, int out_size) {
    const float* x     = (const float*)d_in[0];
    const float* W1    = (const float*)d_in[1];
    const float* b1    = (const float*)d_in[2];
    const float* g1    = (const float*)d_in[3];
    const float* beta1 = (const float*)d_in[4];
    const float* W2    = (const float*)d_in[5];
    const float* b2    = (const float*)d_in[6];
    const float* g2    = (const float*)d_in[7];
    const float* beta2 = (const float*)d_in[8];
    const float* W3    = (const float*)d_in[9];
    const float* b3    = (const float*)d_in[10];
    const float* Wc    = (const float*)d_in[11];
    const float* bc    = (const float*)d_in[12];
    float* out = (float*)d_out;

    __nv_bfloat16 *p_xh, *p_w1h, *p_a1h, *p_w2h, *p_h2;
    float *p_pd, *p_sum1, *p_sq1, *p_sum2, *p_sq2, *p_b2eff;
    cudaGetSymbolAddress((void**)&p_xh, g_xh);
    cudaGetSymbolAddress((void**)&p_w1h, g_w1h);
    cudaGetSymbolAddress((void**)&p_a1h, g_a1h);
    cudaGetSymbolAddress((void**)&p_w2h, g_w2h);
    cudaGetSymbolAddress((void**)&p_h2, g_h2);
    cudaGetSymbolAddress((void**)&p_pd, g_pd);
    cudaGetSymbolAddress((void**)&p_sum1, g_sum1);
    cudaGetSymbolAddress((void**)&p_sq1, g_sq1);
    cudaGetSymbolAddress((void**)&p_sum2, g_sum2);
    cudaGetSymbolAddress((void**)&p_sq2, g_sq2);
    cudaGetSymbolAddress((void**)&p_b2eff, g_b2eff);   // device address (the r12 bug
                                                       // passed the host shadow of
                                                       // g_b2eff here -> zeros via ATS)

    const int GSM = 3 * 32768 + 1024;  // 3 stages of 32KB + alignment slack
    cudaFuncSetAttribute(gemm_mma<KIN, H1, true>,
                         cudaFuncAttributeMaxDynamicSharedMemorySize, GSM);
    cudaFuncSetAttribute(gemm_mma<H1, H2N, false>,
                         cudaFuncAttributeMaxDynamicSharedMemorySize, GSM);

    // 1. prep: stats-zero/wsym/w3c | W1 transpose | x->bf16  (one launch)
    mega_prep<<<8 + 2048 + 16384, 256>>>(x, W1, b2, Wc, W3, b3, bc, p_xh, p_w1h);

    // 2. gemm1 (1024 tile blocks) + pairdot (2048 tail-fill blocks)
    gemm_mma<KIN, H1, true><<<1024 + 2048, 256, GSM>>>(
        p_xh, p_w1h, b1, p_a1h, p_sum1, p_sq1, x, p_pd);

    // 3. fold BN1 into W2 + b2eff (stats computed inline)
    mega_fold<<<512 + 64, 256>>>(W2, g1, beta1, p_w2h);

    // 4. gemm2: h2 = relu(a1 @ (scale1*W2) + b2eff), fused BN2 stats  [profiled]
    gemm_mma<H1, H2N, false><<<512, 256, GSM>>>(
        p_a1h, p_w2h, p_b2eff, p_h2, p_sum2, p_sq2, nullptr, nullptr);

    // 5. final: BN2 stats inline + (h2 . w3c) + pair term
    final_kernel<<<B_SZ / 8, 256>>>(p_h2, g2, beta2, out);
}

// round 17
// speedup vs baseline: 1.0467x; 1.0467x over previous
#include <cuda_runtime.h>
#include <cuda_bf16.h>
#include <cstdint>

// ---------------- problem constants ----------------
#define B_SZ   16384
#define NFEAT  32
#define DDIM   64
#define KIN    2048     // NFEAT*DDIM
#define H1     1024
#define H2N    512
#define HOFD   64
#define NPAIRS 496
#define BN_EPS 1e-5f
#define INV_B  (1.0f / 16384.0f)

// ---------------- scratch (device globals; no runtime alloc) ----------------
__device__ __nv_bfloat16 g_xh[(size_t)B_SZ * KIN];
__device__ __nv_bfloat16 g_w1h[(size_t)H1 * KIN];   // [N=H1][K=KIN] transposed
__device__ __nv_bfloat16 g_a1h[(size_t)B_SZ * H1];  // relu(x@W1+b1) bf16, pre-BN
__device__ __nv_bfloat16 g_w2h[(size_t)H2N * H1];   // [N=H2N][K=H1], scale1 folded
__device__ __nv_bfloat16 g_h2[(size_t)B_SZ * H2N];  // relu bf16, pre-BN2
__device__ float g_pd[B_SZ];
__device__ float g_sum1[H1], g_sq1[H1];
__device__ float g_sum2[H2N], g_sq2[H2N];
__device__ float g_b2eff[H2N];
__device__ float g_w3c[H2N + 1];

// ================= PTX helpers (baseline ISA only) ========
__device__ __forceinline__ uint32_t smem_u32(const void* p) {
    uint32_t a;
    asm("{ .reg .u64 t; cvta.to.shared.u64 t, %1; cvt.u32.u64 %0, t; }"
        : "=r"(a) : "l"(p));
    return a;
}
__device__ __forceinline__ void cpa16(uint32_t s, const void* g) {
    asm volatile("cp.async.cg.shared.global [%0], [%1], 16;" :: "r"(s), "l"(g));
}
#define CP_COMMIT() asm volatile("cp.async.commit_group;" ::: "memory")
#define CP_WAIT1()  asm volatile("cp.async.wait_group 1;" ::: "memory")
#define SWZ(o)      ((o) ^ (((o) >> 3) & 0x70))

__device__ __forceinline__ void ldsm4(uint32_t& r0, uint32_t& r1,
                                      uint32_t& r2, uint32_t& r3, uint32_t a) {
    asm volatile("ldmatrix.sync.aligned.m8n8.x4.shared.b16 {%0,%1,%2,%3}, [%4];"
                 : "=r"(r0), "=r"(r1), "=r"(r2), "=r"(r3) : "r"(a));
}
__device__ __forceinline__ void mma16816(float* c,
                                         uint32_t a0, uint32_t a1, uint32_t a2, uint32_t a3,
                                         uint32_t b0, uint32_t b1) {
    asm volatile("mma.sync.aligned.m16n8k16.row.col.f32.bf16.bf16.f32 "
                 "{%0,%1,%2,%3}, {%4,%5,%6,%7}, {%8,%9}, {%0,%1,%2,%3};"
                 : "+f"(c[0]), "+f"(c[1]), "+f"(c[2]), "+f"(c[3])
                 : "r"(a0), "r"(a1), "r"(a2), "r"(a3), "r"(b0), "r"(b1));
}

// ================= bf16 HMMA GEMM + fused BN stats =========================
// 128x128 tile, 8 warps (2x4, warp tile 64x32), 3-stage cp.async, 2 CTAs/SM.
// C = relu(A @ B^T + bias) written bf16; per-column sum/sum^2 atomics.
template<int KDIM, int NTOT>
__global__ __launch_bounds__(256, 2) void gemm_mma(
    const __nv_bfloat16* __restrict__ A,
    const __nv_bfloat16* __restrict__ Bw,
    const float* __restrict__ bias,
    __nv_bfloat16* __restrict__ outH,
    float* __restrict__ sumP, float* __restrict__ sqP)
{
    constexpr int S = 3, BK = 64, BN = 128, BM = 128;
    constexpr int T = KDIM / BK;
    constexpr int NT = NTOT / BN;
    constexpr int STAGE_BYTES = (BM + BN) * 128;  // 32KB

    extern __shared__ char smraw[];
    const int tid = threadIdx.x;
    const int wid = tid >> 5, lane = tid & 31;

    const uint32_t sb = (smem_u32(smraw) + 1023) & ~1023u;
    const int wm0 = (wid >> 2) * 64;
    const int wn0 = (wid & 3) * 32;
    const int n0 = (blockIdx.x % NT) * BN;
    const int m0 = (blockIdx.x / NT) * BM;

    auto load_stage = [&](int gs) {
        const uint32_t sA = sb + (gs % S) * STAGE_BYTES;
        const uint32_t sB = sA + BM * 128;
        const int kk = gs * BK;
        const __nv_bfloat16* Ab = A + (size_t)m0 * KDIM + kk;
        const __nv_bfloat16* Bb = Bw + (size_t)n0 * KDIM + kk;
        #pragma unroll
        for (int t = 0; t < BM * 8 / 256; t++) {
            int c = tid + t * 256;
            int r = c >> 3, ch = c & 7;
            cpa16(sA + SWZ(r * 128 + ch * 16), Ab + (size_t)r * KDIM + ch * 8);
        }
        #pragma unroll
        for (int t = 0; t < BN * 8 / 256; t++) {
            int c = tid + t * 256;
            int r = c >> 3, ch = c & 7;
            cpa16(sB + SWZ(r * 128 + ch * 16), Bb + (size_t)r * KDIM + ch * 8);
        }
    };

    load_stage(0); CP_COMMIT();
    load_stage(1); CP_COMMIT();

    float acc[4][4][4];
    #pragma unroll
    for (int i = 0; i < 4; i++)
        #pragma unroll
        for (int j = 0; j < 4; j++)
            #pragma unroll
            for (int r = 0; r < 4; r++) acc[i][j][r] = 0.f;

    const int aRowOff = (wm0 + (lane & 15)) * 128 + (lane >> 4) * 16;
    const int bRowBase = (wn0 + (lane & 7) + ((lane >> 4) << 3)) * 128 +
                         (((lane >> 3) & 1) << 4);

    for (int i = 0; i < T; ++i) {
        CP_WAIT1();
        __syncthreads();
        const uint32_t sA = sb + (i % S) * STAGE_BYTES;
        const uint32_t sB = sA + BM * 128;
        #pragma unroll
        for (int ks = 0; ks < 4; ks++) {
            const int kb = ks * 32;
            uint32_t a[4][4];
            #pragma unroll
            for (int mi = 0; mi < 4; mi++)
                ldsm4(a[mi][0], a[mi][1], a[mi][2], a[mi][3],
                      sA + SWZ(aRowOff + mi * 16 * 128 + kb));
            uint32_t bf[2][4];
            #pragma unroll
            for (int gg = 0; gg < 2; gg++)
                ldsm4(bf[gg][0], bf[gg][1], bf[gg][2], bf[gg][3],
                      sB + SWZ(bRowBase + gg * 16 * 128 + kb));
            #pragma unroll
            for (int mi = 0; mi < 4; mi++)
                #pragma unroll
                for (int j = 0; j < 4; j++)
                    mma16816(acc[mi][j], a[mi][0], a[mi][1], a[mi][2], a[mi][3],
                             bf[j >> 1][(j & 1) * 2], bf[j >> 1][(j & 1) * 2 + 1]);
        }
        const int ns = i + 2;
        if (ns < T) load_stage(ns);
        CP_COMMIT();
    }

    // epilogue: relu+bias, bf16 store, fused column stats
    float csum[4][2], csq[4][2];
    #pragma unroll
    for (int j = 0; j < 4; j++) { csum[j][0] = csum[j][1] = csq[j][0] = csq[j][1] = 0.f; }

    #pragma unroll
    for (int j = 0; j < 4; j++) {
        const int col = n0 + wn0 + j * 8 + (lane & 3) * 2;
        const float bi0 = bias[col], bi1 = bias[col + 1];
        #pragma unroll
        for (int mi = 0; mi < 4; mi++) {
            const int row = m0 + wm0 + mi * 16 + (lane >> 2);
            #pragma unroll
            for (int h = 0; h < 2; h++) {
                const int rr = row + h * 8;
                const float v0 = fmaxf(acc[mi][j][2 * h + 0] + bi0, 0.f);
                const float v1 = fmaxf(acc[mi][j][2 * h + 1] + bi1, 0.f);
                __nv_bfloat162 ph;
                ph.x = __float2bfloat16(v0);
                ph.y = __float2bfloat16(v1);
                *(__nv_bfloat162*)(outH + (size_t)rr * NTOT + col) = ph;
                csum[j][0] += v0; csq[j][0] = fmaf(v0, v0, csq[j][0]);
                csum[j][1] += v1; csq[j][1] = fmaf(v1, v1, csq[j][1]);
            }
        }
    }
    #pragma unroll
    for (int j = 0; j < 4; j++)
        #pragma unroll
        for (int c = 0; c < 2; c++) {
            #pragma unroll
            for (int o = 16; o >= 4; o >>= 1) {
                csum[j][c] += __shfl_down_sync(0xffffffffu, csum[j][c], o);
                csq[j][c]  += __shfl_down_sync(0xffffffffu, csq[j][c],  o);
            }
        }
    if (lane < 4) {
        #pragma unroll
        for (int j = 0; j < 4; j++)
            #pragma unroll
            for (int c = 0; c < 2; c++) {
                const int col = n0 + wn0 + j * 8 + lane * 2 + c;
                atomicAdd(&sumP[col], csum[j][c]);
                atomicAdd(&sqP[col],  csq[j][c]);
            }
    }
}

// ================= mega prep kernel ========================================
// blocks [0, 2048):    pairdot + x->bf16 fused (single pass over x)
// blocks [2048, 4096): W1 transpose->bf16
// blocks [4096, 4102): stat zero + b2eff init + w3c
__global__ __launch_bounds__(256) void mega_prep(
    const float* __restrict__ x, const float* __restrict__ W1,
    const float* __restrict__ b2, const float* __restrict__ Wc,
    const float* __restrict__ W3, const float* __restrict__ b3,
    const float* __restrict__ bc,
    __nv_bfloat16* __restrict__ xh, __nv_bfloat16* __restrict__ w1h,
    float* __restrict__ pd)
{
    __shared__ float tt[32][33];
    __shared__ float Ws[NFEAT * NFEAT];
    const int t = threadIdx.x;
    const int blk = blockIdx.x;

    if (blk < 2048) {
        // ---- fused pairdot + conversion: read x once, write xh, compute pd ----
        // Ws built locally from Wc (closed-form triu index; no global, no race)
        for (int idx = t; idx < NFEAT * NFEAT; idx += 256) {
            const int i = idx >> 5, j = idx & 31;
            float w = 0.f;
            if (i != j) {
                const int a = i < j ? i : j;
                const int bb = i < j ? j : i;
                const int p = a * (63 - a) / 2 + (bb - a - 1);
                w = 0.5f * Wc[HOFD + p];
            }
            Ws[idx] = w;
        }
        __syncthreads();

        const int wid = t >> 5, lane = t & 31;
        const int b = blk * 8 + wid;
        const float2* xp = (const float2*)(x + (size_t)b * KIN) + lane;
        __nv_bfloat162* xo = (__nv_bfloat162*)(xh + (size_t)b * KIN) + lane;

        float xa[NFEAT], xb[NFEAT];
        #pragma unroll
        for (int n = 0; n < NFEAT; n++) {
            float2 v = xp[n * 32];             // coalesced 256B per feature
            xa[n] = v.x; xb[n] = v.y;
            __nv_bfloat162 h;
            h.x = __float2bfloat16(v.x);
            h.y = __float2bfloat16(v.y);
            xo[n * 32] = h;                    // coalesced 128B per feature
        }

        float acc = 0.f;
        #pragma unroll
        for (int n = 0; n < NFEAT; n++) {
            float ta = 0.f, tb = 0.f;
            const float4* wrow = (const float4*)&Ws[n * NFEAT];
            #pragma unroll
            for (int m4 = 0; m4 < NFEAT / 4; m4++) {
                float4 w = wrow[m4];
                const int m = m4 * 4;
                ta = fmaf(w.x, xa[m + 0], ta); tb = fmaf(w.x, xb[m + 0], tb);
                ta = fmaf(w.y, xa[m + 1], ta); tb = fmaf(w.y, xb[m + 1], tb);
                ta = fmaf(w.z, xa[m + 2], ta); tb = fmaf(w.z, xb[m + 2], tb);
                ta = fmaf(w.w, xa[m + 3], ta); tb = fmaf(w.w, xb[m + 3], tb);
            }
            acc = fmaf(xa[n], ta, acc);
            acc = fmaf(xb[n], tb, acc);
        }
        #pragma unroll
        for (int o = 16; o > 0; o >>= 1)
            acc += __shfl_down_sync(0xffffffffu, acc, o);
        if (lane == 0) pd[b] = acc;
    } else if (blk < 4096) {
        // ---- W1 [KIN][H1] -> w1h [H1][KIN] bf16 ----
        const int id = blk - 2048;
        const int lx = t & 31, ly = t >> 5;
        const int n0 = (id & 31) * 32;          // H1/32 = 32 tiles
        const int k0 = (id >> 5) * 32;          // KIN/32 = 64 tiles
        #pragma unroll
        for (int r = 0; r < 4; r++)
            tt[ly + r * 8][lx] = W1[(size_t)(k0 + ly + r * 8) * H1 + n0 + lx];
        __syncthreads();
        #pragma unroll
        for (int r = 0; r < 4; r++) {
            int n = n0 + ly + r * 8;
            w1h[(size_t)n * KIN + k0 + lx] = __float2bfloat16(tt[lx][ly + r * 8]);
        }
    } else if (blk < 4100) {
        const int i = (blk - 4096) * 256 + t;
        if (i < H1)  { g_sum1[i] = 0.f; g_sq1[i] = 0.f; }
        if (i < H2N) { g_sum2[i] = 0.f; g_sq2[i] = 0.f; g_b2eff[i] = b2[i]; }
    } else {
        const int k = (blk - 4100) * 256 + t;   // 0..511
        if (k < H2N) {
            float s = 0.f;
            #pragma unroll
            for (int j = 0; j < HOFD; j++) s += W3[k * HOFD + j] * Wc[j];
            g_w3c[k] = s;
        }
        if (blk == 4100 && t == 0) {
            float s = 0.f;
            #pragma unroll
            for (int j = 0; j < HOFD; j++) s += b3[j] * Wc[j];
            g_w3c[H2N] = s + bc[0];
        }
    }
}

// ================= fold kernel: BN1 -> W2 / b2eff (stats inline) ===========
// blocks 0-511: W2 transpose with scale1 fold; blocks 512-575: b2eff rank-1
__global__ __launch_bounds__(256) void mega_fold(
    const float* __restrict__ W2, const float* __restrict__ g1,
    const float* __restrict__ beta1, __nv_bfloat16* __restrict__ w2h)
{
    __shared__ float tt[32][33];
    __shared__ float sv[32];
    const int t = threadIdx.x;
    const int lx = t & 31, ly = t >> 5;
    if (blockIdx.x < 512) {
        const int id = blockIdx.x;
        const int n0 = (id & 15) * 32;          // H2N/32 = 16 tiles
        const int k0 = (id >> 4) * 32;          // H1/32 = 32 tiles
        if (t < 32) {
            const int k = k0 + t;
            float m = g_sum1[k] * INV_B;
            float var = g_sq1[k] * INV_B - m * m;
            sv[t] = g1[k] * rsqrtf(var + BN_EPS);
        }
        __syncthreads();
        #pragma unroll
        for (int r = 0; r < 4; r++) {
            const int kk = ly + r * 8;
            tt[kk][lx] = W2[(size_t)(k0 + kk) * H2N + n0 + lx] * sv[kk];
        }
        __syncthreads();
        #pragma unroll
        for (int r = 0; r < 4; r++) {
            int n = n0 + ly + r * 8;
            w2h[(size_t)n * H1 + k0 + lx] = __float2bfloat16(tt[lx][ly + r * 8]);
        }
    } else {
        const int k0 = (blockIdx.x - 512) * 16;
        if (t < 16) {
            const int k = k0 + t;
            float m = g_sum1[k] * INV_B;
            float var = g_sq1[k] * INV_B - m * m;
            float s = g1[k] * rsqrtf(var + BN_EPS);
            sv[t] = beta1[k] - m * s;       // bias1v
        }
        __syncthreads();
        #pragma unroll
        for (int half = 0; half < 2; half++) {
            const int n = t + half * 256;
            float a = 0.f;
            #pragma unroll
            for (int r = 0; r < 16; r++)
                a += sv[r] * W2[(size_t)(k0 + r) * H2N + n];
            atomicAdd(&g_b2eff[n], a);
        }
    }
}

// ================= final: BN2 stats inline + dot + pair term ===============
__global__ __launch_bounds__(256) void final_kernel(
    const __nv_bfloat16* __restrict__ h2, const float* __restrict__ g2,
    const float* __restrict__ beta2, float* __restrict__ out)
{
    __shared__ float sc2[H2N], bv2[H2N];
    const int t = threadIdx.x;
    for (int j = t; j < H2N; j += 256) {
        float m = g_sum2[j] * INV_B;
        float var = g_sq2[j] * INV_B - m * m;
        float s = g2[j] * rsqrtf(var + BN_EPS);
        float w = g_w3c[j];
        sc2[j] = s * w;
        bv2[j] = (beta2[j] - m * s) * w;
    }
    __syncthreads();
    const int wid = t >> 5, lane = t & 31;
    const int gw = blockIdx.x * 8 + wid;
    const __nv_bfloat162* h = (const __nv_bfloat162*)(h2 + (size_t)gw * H2N) + lane;
    float acc = 0.f;
    #pragma unroll
    for (int it = 0; it < H2N / 64; it++) {
        const int k = it * 64 + lane * 2;
        __nv_bfloat162 hv = h[it * 32];
        acc += fmaf(__bfloat162float(hv.x), sc2[k],     bv2[k]);
        acc += fmaf(__bfloat162float(hv.y), sc2[k + 1], bv2[k + 1]);
    }
    #pragma unroll
    for (int o = 16; o > 0; o >>= 1)
        acc += __shfl_down_sync(0xffffffffu, acc, o);
    if (lane == 0) out[gw] = acc + g_w3c[H2N] + g_pd[gw];
}

// ================= launch =================
extern "C" void kernel_launch(void* const* d_in, const int* in_sizes, int n_in,
                              void* d_out, int out_size) {
    const float* x     = (const float*)d_in[0];
    const float* W1    = (const float*)d_in[1];
    const float* b1    = (const float*)d_in[2];
    const float* g1    = (const float*)d_in[3];
    const float* beta1 = (const float*)d_in[4];
    const float* W2    = (const float*)d_in[5];
    const float* b2    = (const float*)d_in[6];
    const float* g2    = (const float*)d_in[7];
    const float* beta2 = (const float*)d_in[8];
    const float* W3    = (const float*)d_in[9];
    const float* b3    = (const float*)d_in[10];
    const float* Wc    = (const float*)d_in[11];
    const float* bc    = (const float*)d_in[12];
    float* out = (float*)d_out;

    __nv_bfloat16 *p_xh, *p_w1h, *p_a1h, *p_w2h, *p_h2;
    float *p_pd, *p_sum1, *p_sq1, *p_sum2, *p_sq2, *p_b2eff;
    cudaGetSymbolAddress((void**)&p_xh, g_xh);
    cudaGetSymbolAddress((void**)&p_w1h, g_w1h);
    cudaGetSymbolAddress((void**)&p_a1h, g_a1h);
    cudaGetSymbolAddress((void**)&p_w2h, g_w2h);
    cudaGetSymbolAddress((void**)&p_h2, g_h2);
    cudaGetSymbolAddress((void**)&p_pd, g_pd);
    cudaGetSymbolAddress((void**)&p_sum1, g_sum1);
    cudaGetSymbolAddress((void**)&p_sq1, g_sq1);
    cudaGetSymbolAddress((void**)&p_sum2, g_sum2);
    cudaGetSymbolAddress((void**)&p_sq2, g_sq2);
    cudaGetSymbolAddress((void**)&p_b2eff, g_b2eff);

    const int GSM = 3 * 32768 + 1024;  // 3 stages of 32KB + alignment slack
    cudaFuncSetAttribute(gemm_mma<KIN, H1>,
                         cudaFuncAttributeMaxDynamicSharedMemorySize, GSM);
    cudaFuncSetAttribute(gemm_mma<H1, H2N>,
                         cudaFuncAttributeMaxDynamicSharedMemorySize, GSM);

    // 1. prep: pairdot+x->bf16 fused | W1 transpose | stats/w3c  (one launch)
    mega_prep<<<4102, 256>>>(x, W1, b2, Wc, W3, b3, bc, p_xh, p_w1h, p_pd);

    // 2. gemm1: a1 = relu(x @ W1 + b1), bf16 out + fused BN1 stats
    gemm_mma<KIN, H1><<<1024, 256, GSM>>>(
        p_xh, p_w1h, b1, p_a1h, p_sum1, p_sq1);

    // 3. fold BN1 into W2 + b2eff (stats computed inline)
    mega_fold<<<512 + 64, 256>>>(W2, g1, beta1, p_w2h);

    // 4. gemm2: h2 = relu(a1 @ (scale1*W2) + b2eff), fused BN2 stats  [profiled]
    gemm_mma<H1, H2N><<<512, 256, GSM>>>(
        p_a1h, p_w2h, p_b2eff, p_h2, p_sum2, p_sq2);

    // 5. final: BN2 stats inline + (h2 . w3c) + pair term
    final_kernel<<<B_SZ / 8, 256>>>(p_h2, g2, beta2, out);
}